// round 3
// baseline (speedup 1.0000x reference)
#include <cuda_runtime.h>
#include <cuda_bf16.h>

// ---------------- problem constants ----------------
#define NB   8
#define NC   2048
#define NF   8192
#define CDIM 256
#define CS   64
#define OUTD 256
#define MTOT (NB*NF)        // 65536 fine points
#define K1   (CDIM+CS)      // 320
#define HSIZE (MTOT*OUTD)   // 16777216 floats for h

// ---------------- scratch (static device globals; no allocation) ----------------
__device__ int   g_idx[MTOT*3];
__device__ float g_w[MTOT*3];
__device__ float g_h1[HSIZE];   // 64 MB intermediate after first Linear+ReLU

// ---------------- 1) brute-force KNN (K=3) per cloud ----------------
__global__ void knn_kernel(const float* __restrict__ pos,
                           const float* __restrict__ pos_skip) {
    __shared__ float sp[NC*3];          // 24 KB coarse positions for this cloud
    int b = blockIdx.x >> 5;            // 32 blocks per cloud
    int p_local = ((blockIdx.x & 31) << 8) + threadIdx.x;
    const float* cp = pos + (size_t)b * NC * 3;
    for (int i = threadIdx.x; i < NC*3; i += blockDim.x) sp[i] = cp[i];
    __syncthreads();

    int p = b * NF + p_local;
    float fx = pos_skip[p*3+0], fy = pos_skip[p*3+1], fz = pos_skip[p*3+2];

    float d0 = 1e30f, d1 = 1e30f, d2 = 1e30f;
    int   i0 = 0,     i1 = 0,     i2 = 0;

    #pragma unroll 4
    for (int j = 0; j < NC; j++) {
        float dx = fx - sp[j*3+0];
        float dy = fy - sp[j*3+1];
        float dz = fz - sp[j*3+2];
        float d = dx*dx + dy*dy + dz*dz;
        if (d < d2) {
            if (d < d1) {
                d2 = d1; i2 = i1;
                if (d < d0) { d1 = d0; i1 = i0; d0 = d; i0 = j; }
                else        { d1 = d;  i1 = j; }
            } else { d2 = d; i2 = j; }
        }
    }

    float w0 = 1.0f / fmaxf(d0, 1e-16f);
    float w1 = 1.0f / fmaxf(d1, 1e-16f);
    float w2 = 1.0f / fmaxf(d2, 1e-16f);
    float inv = 1.0f / (w0 + w1 + w2);
    g_idx[p*3+0] = b*NC + i0;
    g_idx[p*3+1] = b*NC + i1;
    g_idx[p*3+2] = b*NC + i2;
    g_w[p*3+0] = w0 * inv;
    g_w[p*3+1] = w1 * inv;
    g_w[p*3+2] = w2 * inv;
}

// ---------------- GEMM tiling parameters ----------------
#define BM 128
#define BN 128
#define BK 16
#define PAD 4

// ---------------- 2) fused interp-gather + concat + Linear1 + ReLU ----------------
__global__ __launch_bounds__(256)
void gemm1_kernel(const float* __restrict__ x,
                  const float* __restrict__ x_skip,
                  const float* __restrict__ W1,
                  const float* __restrict__ b1) {
    __shared__ float As[BK][BM+PAD];
    __shared__ float Bs[BK][BN+PAD];

    int tid = threadIdx.x;
    int bm = blockIdx.y * BM;
    int bn = blockIdx.x * BN;
    int tx = tid & 15;
    int ty = tid >> 4;

    int a_r = tid >> 2;
    int a_c = (tid & 3) << 2;
    int b_r = tid >> 5;
    int b_c = (tid & 31) << 2;

    int r0 = bm + a_r, r1 = r0 + 64;
    int i00 = g_idx[r0*3+0] * CDIM, i01 = g_idx[r0*3+1] * CDIM, i02 = g_idx[r0*3+2] * CDIM;
    int i10 = g_idx[r1*3+0] * CDIM, i11 = g_idx[r1*3+1] * CDIM, i12 = g_idx[r1*3+2] * CDIM;
    float w00 = g_w[r0*3+0], w01 = g_w[r0*3+1], w02 = g_w[r0*3+2];
    float w10 = g_w[r1*3+0], w11 = g_w[r1*3+1], w12 = g_w[r1*3+2];

    float acc[8][8];
    #pragma unroll
    for (int i = 0; i < 8; i++)
        #pragma unroll
        for (int j = 0; j < 8; j++) acc[i][j] = 0.0f;

    for (int kt = 0; kt < K1; kt += BK) {
        if (kt < CDIM) {
            int k = kt + a_c;
            float4 p0 = *(const float4*)(x + i00 + k);
            float4 p1 = *(const float4*)(x + i01 + k);
            float4 p2 = *(const float4*)(x + i02 + k);
            As[a_c+0][a_r] = w00*p0.x + w01*p1.x + w02*p2.x;
            As[a_c+1][a_r] = w00*p0.y + w01*p1.y + w02*p2.y;
            As[a_c+2][a_r] = w00*p0.z + w01*p1.z + w02*p2.z;
            As[a_c+3][a_r] = w00*p0.w + w01*p1.w + w02*p2.w;
            p0 = *(const float4*)(x + i10 + k);
            p1 = *(const float4*)(x + i11 + k);
            p2 = *(const float4*)(x + i12 + k);
            As[a_c+0][a_r+64] = w10*p0.x + w11*p1.x + w12*p2.x;
            As[a_c+1][a_r+64] = w10*p0.y + w11*p1.y + w12*p2.y;
            As[a_c+2][a_r+64] = w10*p0.z + w11*p1.z + w12*p2.z;
            As[a_c+3][a_r+64] = w10*p0.w + w11*p1.w + w12*p2.w;
        } else {
            int k = kt + a_c - CDIM;
            float4 v = *(const float4*)(x_skip + r0*CS + k);
            As[a_c+0][a_r] = v.x; As[a_c+1][a_r] = v.y;
            As[a_c+2][a_r] = v.z; As[a_c+3][a_r] = v.w;
            v = *(const float4*)(x_skip + r1*CS + k);
            As[a_c+0][a_r+64] = v.x; As[a_c+1][a_r+64] = v.y;
            As[a_c+2][a_r+64] = v.z; As[a_c+3][a_r+64] = v.w;
        }
        {
            float4 v = *(const float4*)(W1 + (kt + b_r) * OUTD + bn + b_c);
            Bs[b_r][b_c+0] = v.x; Bs[b_r][b_c+1] = v.y;
            Bs[b_r][b_c+2] = v.z; Bs[b_r][b_c+3] = v.w;
            v = *(const float4*)(W1 + (kt + b_r + 8) * OUTD + bn + b_c);
            Bs[b_r+8][b_c+0] = v.x; Bs[b_r+8][b_c+1] = v.y;
            Bs[b_r+8][b_c+2] = v.z; Bs[b_r+8][b_c+3] = v.w;
        }
        __syncthreads();

        #pragma unroll
        for (int k = 0; k < BK; k++) {
            float4 a0 = *(const float4*)&As[k][ty*8];
            float4 a1 = *(const float4*)&As[k][ty*8+4];
            float4 c0 = *(const float4*)&Bs[k][tx*8];
            float4 c1 = *(const float4*)&Bs[k][tx*8+4];
            float ar[8] = {a0.x,a0.y,a0.z,a0.w,a1.x,a1.y,a1.z,a1.w};
            float br[8] = {c0.x,c0.y,c0.z,c0.w,c1.x,c1.y,c1.z,c1.w};
            #pragma unroll
            for (int i = 0; i < 8; i++)
                #pragma unroll
                for (int j = 0; j < 8; j++)
                    acc[i][j] += ar[i] * br[j];
        }
        __syncthreads();
    }

    #pragma unroll
    for (int i = 0; i < 8; i++) {
        int row = bm + ty*8 + i;
        #pragma unroll
        for (int j = 0; j < 8; j += 4) {
            int col = bn + tx*8 + j;
            float4 o;
            o.x = fmaxf(acc[i][j+0] + b1[col+0], 0.0f);
            o.y = fmaxf(acc[i][j+1] + b1[col+1], 0.0f);
            o.z = fmaxf(acc[i][j+2] + b1[col+2], 0.0f);
            o.w = fmaxf(acc[i][j+3] + b1[col+3], 0.0f);
            *(float4*)(g_h1 + (size_t)row * OUTD + col) = o;
        }
    }
}

// ---------------- 3) Linear2 + ReLU: out = relu(g_h1 @ W2 + b2) ----------------
__global__ __launch_bounds__(256)
void gemm2_kernel(const float* __restrict__ W2,
                  const float* __restrict__ b2,
                  float* __restrict__ out) {
    __shared__ float As[BK][BM+PAD];
    __shared__ float Bs[BK][BN+PAD];

    int tid = threadIdx.x;
    int bm = blockIdx.y * BM;
    int bn = blockIdx.x * BN;
    int tx = tid & 15;
    int ty = tid >> 4;

    int a_r = tid >> 2;
    int a_c = (tid & 3) << 2;
    int b_r = tid >> 5;
    int b_c = (tid & 31) << 2;

    int r0 = bm + a_r, r1 = r0 + 64;

    float acc[8][8];
    #pragma unroll
    for (int i = 0; i < 8; i++)
        #pragma unroll
        for (int j = 0; j < 8; j++) acc[i][j] = 0.0f;

    for (int kt = 0; kt < OUTD; kt += BK) {
        int k = kt + a_c;
        float4 v = *(const float4*)(g_h1 + (size_t)r0 * OUTD + k);
        As[a_c+0][a_r] = v.x; As[a_c+1][a_r] = v.y;
        As[a_c+2][a_r] = v.z; As[a_c+3][a_r] = v.w;
        v = *(const float4*)(g_h1 + (size_t)r1 * OUTD + k);
        As[a_c+0][a_r+64] = v.x; As[a_c+1][a_r+64] = v.y;
        As[a_c+2][a_r+64] = v.z; As[a_c+3][a_r+64] = v.w;

        v = *(const float4*)(W2 + (kt + b_r) * OUTD + bn + b_c);
        Bs[b_r][b_c+0] = v.x; Bs[b_r][b_c+1] = v.y;
        Bs[b_r][b_c+2] = v.z; Bs[b_r][b_c+3] = v.w;
        v = *(const float4*)(W2 + (kt + b_r + 8) * OUTD + bn + b_c);
        Bs[b_r+8][b_c+0] = v.x; Bs[b_r+8][b_c+1] = v.y;
        Bs[b_r+8][b_c+2] = v.z; Bs[b_r+8][b_c+3] = v.w;
        __syncthreads();

        #pragma unroll
        for (int k2 = 0; k2 < BK; k2++) {
            float4 a0 = *(const float4*)&As[k2][ty*8];
            float4 a1 = *(const float4*)&As[k2][ty*8+4];
            float4 c0 = *(const float4*)&Bs[k2][tx*8];
            float4 c1 = *(const float4*)&Bs[k2][tx*8+4];
            float ar[8] = {a0.x,a0.y,a0.z,a0.w,a1.x,a1.y,a1.z,a1.w};
            float br[8] = {c0.x,c0.y,c0.z,c0.w,c1.x,c1.y,c1.z,c1.w};
            #pragma unroll
            for (int i = 0; i < 8; i++)
                #pragma unroll
                for (int j = 0; j < 8; j++)
                    acc[i][j] += ar[i] * br[j];
        }
        __syncthreads();
    }

    #pragma unroll
    for (int i = 0; i < 8; i++) {
        int row = bm + ty*8 + i;
        #pragma unroll
        for (int j = 0; j < 8; j += 4) {
            int col = bn + tx*8 + j;
            float4 o;
            o.x = fmaxf(acc[i][j+0] + b2[col+0], 0.0f);
            o.y = fmaxf(acc[i][j+1] + b2[col+1], 0.0f);
            o.z = fmaxf(acc[i][j+2] + b2[col+2], 0.0f);
            o.w = fmaxf(acc[i][j+3] + b2[col+3], 0.0f);
            *(float4*)(out + (size_t)row * OUTD + col) = o;
        }
    }
}

// ---------------- 4) tail: pos_skip (f32) + batch_skip (int32 in, f32 out) ----------------
__global__ void aux_kernel(const float* __restrict__ pos_skip,
                           const int* __restrict__ batch_skip,
                           float* __restrict__ out) {
    int i = blockIdx.x * blockDim.x + threadIdx.x;
    if (i < MTOT*3) out[HSIZE + i] = pos_skip[i];
    if (i < MTOT)   out[HSIZE + MTOT*3 + i] = (float)batch_skip[i];
}

// ---------------- launch ----------------
extern "C" void kernel_launch(void* const* d_in, const int* in_sizes, int n_in,
                              void* d_out, int out_size) {
    const float* x          = (const float*)d_in[0];
    const float* pos        = (const float*)d_in[1];
    // d_in[2] = batch (unused; contiguous layout assumed)
    const float* x_skip     = (const float*)d_in[3];
    const float* pos_skip   = (const float*)d_in[4];
    const int*   batch_skip = (const int*)d_in[5];
    const float* W1         = (const float*)d_in[6];
    const float* b1         = (const float*)d_in[7];
    const float* W2         = (const float*)d_in[8];
    const float* b2         = (const float*)d_in[9];
    float* out = (float*)d_out;

    knn_kernel<<<NB*32, 256>>>(pos, pos_skip);
    gemm1_kernel<<<dim3(OUTD/BN, MTOT/BM), 256>>>(x, x_skip, W1, b1);
    gemm2_kernel<<<dim3(OUTD/BN, MTOT/BM), 256>>>(W2, b2, out);
    aux_kernel<<<(MTOT*3 + 255) / 256, 256>>>(pos_skip, batch_skip, out);
}

// round 5
// speedup vs baseline: 1.5759x; 1.5759x over previous
#include <cuda_runtime.h>
#include <cuda_bf16.h>
#include <cstdint>

// ---------------- problem constants ----------------
#define NB   8
#define NC   2048
#define NF   8192
#define CDIM 256
#define CS   64
#define OUTD 256
#define MTOT (NB*NF)        // 65536 fine points
#define K1   (CDIM+CS)      // 320
#define HSIZE (MTOT*OUTD)

// ---------------- scratch (static device globals) ----------------
__device__ int   g_idx[MTOT*3];
__device__ float g_w[MTOT*3];
__device__ __nv_bfloat16 g_h_hi[HSIZE];       // 32 MB
__device__ __nv_bfloat16 g_h_lo[HSIZE];       // 32 MB
__device__ __nv_bfloat16 g_w1t_hi[OUTD*K1];   // W1^T [256][320]
__device__ __nv_bfloat16 g_w1t_lo[OUTD*K1];
__device__ __nv_bfloat16 g_w2t_hi[OUTD*OUTD]; // W2^T [256][256]
__device__ __nv_bfloat16 g_w2t_lo[OUTD*OUTD];

// ---------------- helpers ----------------
__device__ __forceinline__ uint32_t smem_u32(const void* p) {
    uint32_t a;
    asm("{ .reg .u64 t; cvta.to.shared.u64 t, %1; cvt.u32.u64 %0, t; }" : "=r"(a) : "l"(p));
    return a;
}

#define LDSM_X4(r0, r1, r2, r3, addr) \
    asm volatile("ldmatrix.sync.aligned.m8n8.x4.shared.b16 {%0,%1,%2,%3}, [%4];" \
        : "=r"(r0), "=r"(r1), "=r"(r2), "=r"(r3) : "r"(addr))

#define MMA_BF16(d, a, b0, b1) \
    asm volatile("mma.sync.aligned.m16n8k16.row.col.f32.bf16.bf16.f32 " \
        "{%0,%1,%2,%3}, {%4,%5,%6,%7}, {%8,%9}, {%0,%1,%2,%3};" \
        : "+f"((d)[0]), "+f"((d)[1]), "+f"((d)[2]), "+f"((d)[3]) \
        : "r"((a)[0]), "r"((a)[1]), "r"((a)[2]), "r"((a)[3]), "r"(b0), "r"(b1))

__device__ __forceinline__ void split2(float v0, float v1, uint32_t& hi, uint32_t& lo) {
    __nv_bfloat16 h0 = __float2bfloat16(v0);
    __nv_bfloat16 h1 = __float2bfloat16(v1);
    __nv_bfloat16 l0 = __float2bfloat16(v0 - __bfloat162float(h0));
    __nv_bfloat16 l1 = __float2bfloat16(v1 - __bfloat162float(h1));
    hi = ((uint32_t)__bfloat16_as_ushort(h1) << 16) | (uint32_t)__bfloat16_as_ushort(h0);
    lo = ((uint32_t)__bfloat16_as_ushort(l1) << 16) | (uint32_t)__bfloat16_as_ushort(l0);
}

// ---------------- 1) brute-force KNN (K=3) per cloud ----------------
__global__ void knn_kernel(const float* __restrict__ pos,
                           const float* __restrict__ pos_skip) {
    __shared__ float sp[NC*3];
    int b = blockIdx.x >> 5;
    int p_local = ((blockIdx.x & 31) << 8) + threadIdx.x;
    const float* cp = pos + (size_t)b * NC * 3;
    for (int i = threadIdx.x; i < NC*3; i += blockDim.x) sp[i] = cp[i];
    __syncthreads();

    int p = b * NF + p_local;
    float fx = pos_skip[p*3+0], fy = pos_skip[p*3+1], fz = pos_skip[p*3+2];

    float d0 = 1e30f, d1 = 1e30f, d2 = 1e30f;
    int   i0 = 0,     i1 = 0,     i2 = 0;

    #pragma unroll 4
    for (int j = 0; j < NC; j++) {
        float dx = fx - sp[j*3+0];
        float dy = fy - sp[j*3+1];
        float dz = fz - sp[j*3+2];
        float d = dx*dx + dy*dy + dz*dz;
        if (d < d2) {
            if (d < d1) {
                d2 = d1; i2 = i1;
                if (d < d0) { d1 = d0; i1 = i0; d0 = d; i0 = j; }
                else        { d1 = d;  i1 = j; }
            } else { d2 = d; i2 = j; }
        }
    }

    float w0 = 1.0f / fmaxf(d0, 1e-16f);
    float w1 = 1.0f / fmaxf(d1, 1e-16f);
    float w2 = 1.0f / fmaxf(d2, 1e-16f);
    float inv = 1.0f / (w0 + w1 + w2);
    g_idx[p*3+0] = b*NC + i0;
    g_idx[p*3+1] = b*NC + i1;
    g_idx[p*3+2] = b*NC + i2;
    g_w[p*3+0] = w0 * inv;
    g_w[p*3+1] = w1 * inv;
    g_w[p*3+2] = w2 * inv;
}

// ---------------- prep: transpose + bf16-split weights ----------------
__global__ void prep_kernel(const float* __restrict__ W1, const float* __restrict__ W2) {
    int t = blockIdx.x * blockDim.x + threadIdx.x;
    if (t < OUTD * K1) {
        int n = t / K1, k = t - n * K1;
        float v = W1[k * OUTD + n];
        __nv_bfloat16 h = __float2bfloat16(v);
        g_w1t_hi[t] = h;
        g_w1t_lo[t] = __float2bfloat16(v - __bfloat162float(h));
    }
    if (t < OUTD * OUTD) {
        int n = t >> 8, k = t & 255;
        float v = W2[k * OUTD + n];
        __nv_bfloat16 h = __float2bfloat16(v);
        g_w2t_hi[t] = h;
        g_w2t_lo[t] = __float2bfloat16(v - __bfloat162float(h));
    }
}

// ---------------- GEMM tile layout ----------------
// SMEM tiles: 128 rows x 32 bf16, padded row stride RS=40 bf16 (80B) -> conflict-free ldmatrix
#define RS 40

struct Frag { uint32_t ah[4][4], al[4][4], bh[2][4], bl[2][4]; };

// ---------------- 2) mma.sync GEMM1: interp-gather + concat + Linear1 + ReLU ----------------
__global__ __launch_bounds__(256)
void gemm1_kernel(const float* __restrict__ x,
                  const float* __restrict__ x_skip,
                  const float* __restrict__ b1) {
    __shared__ __nv_bfloat16 As_hi[128*RS], As_lo[128*RS];
    __shared__ __nv_bfloat16 Bs_hi[128*RS], Bs_lo[128*RS];

    int tid = threadIdx.x;
    int wid = tid >> 5;
    int lane = tid & 31;
    int warp_m = wid & 1;        // 2 warps in M
    int warp_n = wid >> 1;       // 4 warps in N
    int bm = blockIdx.y * 128;
    int bn = blockIdx.x * 128;

    // loader mapping: thread handles row = tid>>1, cols half*16..+15
    int lrow = tid >> 1;
    int lhalf = tid & 1;
    int r = bm + lrow;
    int i0 = g_idx[r*3+0] * CDIM, i1 = g_idx[r*3+1] * CDIM, i2 = g_idx[r*3+2] * CDIM;
    float w0 = g_w[r*3+0], w1 = g_w[r*3+1], w2 = g_w[r*3+2];
    int nrow = bn + lrow;        // B-tile source row (N index)

    // ldmatrix base addresses (bytes offsets into padded tiles)
    uint32_t aOff = (uint32_t)(((warp_m*64 + (lane & 15)) * RS + (lane >> 4) * 8) * 2);
    uint32_t bOff = (uint32_t)(((warp_n*32 + (lane & 15)) * RS + (lane >> 4) * 8) * 2);
    uint32_t sAhi = smem_u32(As_hi) + aOff, sAlo = smem_u32(As_lo) + aOff;
    uint32_t sBhi = smem_u32(Bs_hi) + bOff, sBlo = smem_u32(Bs_lo) + bOff;

    float acc[4][4][4];
    #pragma unroll
    for (int i = 0; i < 4; i++)
        #pragma unroll
        for (int j = 0; j < 4; j++)
            #pragma unroll
            for (int q = 0; q < 4; q++) acc[i][j][q] = 0.0f;

    for (int kt = 0; kt < K1; kt += 32) {
        // ---- build A tile (gather + interp + split) ----
        {
            uint32_t hp[8], lp[8];
            if (kt < CDIM) {
                int k = kt + lhalf * 16;
                #pragma unroll
                for (int q = 0; q < 4; q++) {
                    float4 a = *(const float4*)(x + i0 + k + q*4);
                    float4 b = *(const float4*)(x + i1 + k + q*4);
                    float4 c = *(const float4*)(x + i2 + k + q*4);
                    float v0 = w0*a.x + w1*b.x + w2*c.x;
                    float v1 = w0*a.y + w1*b.y + w2*c.y;
                    float v2 = w0*a.z + w1*b.z + w2*c.z;
                    float v3 = w0*a.w + w1*b.w + w2*c.w;
                    split2(v0, v1, hp[q*2+0], lp[q*2+0]);
                    split2(v2, v3, hp[q*2+1], lp[q*2+1]);
                }
            } else {
                int ks = kt - CDIM + lhalf * 16;
                #pragma unroll
                for (int q = 0; q < 4; q++) {
                    float4 a = *(const float4*)(x_skip + (size_t)r * CS + ks + q*4);
                    split2(a.x, a.y, hp[q*2+0], lp[q*2+0]);
                    split2(a.z, a.w, hp[q*2+1], lp[q*2+1]);
                }
            }
            int base = lrow * RS + lhalf * 16;
            *(uint4*)(As_hi + base)     = make_uint4(hp[0], hp[1], hp[2], hp[3]);
            *(uint4*)(As_hi + base + 8) = make_uint4(hp[4], hp[5], hp[6], hp[7]);
            *(uint4*)(As_lo + base)     = make_uint4(lp[0], lp[1], lp[2], lp[3]);
            *(uint4*)(As_lo + base + 8) = make_uint4(lp[4], lp[5], lp[6], lp[7]);
        }
        // ---- build B tile from W1^T ----
        {
            const __nv_bfloat16* sh = g_w1t_hi + (size_t)nrow * K1 + kt + lhalf * 16;
            const __nv_bfloat16* sl = g_w1t_lo + (size_t)nrow * K1 + kt + lhalf * 16;
            uint4 vh0 = *(const uint4*)(sh);
            uint4 vh1 = *(const uint4*)(sh + 8);
            uint4 vl0 = *(const uint4*)(sl);
            uint4 vl1 = *(const uint4*)(sl + 8);
            int base = lrow * RS + lhalf * 16;
            *(uint4*)(Bs_hi + base)     = vh0;
            *(uint4*)(Bs_hi + base + 8) = vh1;
            *(uint4*)(Bs_lo + base)     = vl0;
            *(uint4*)(Bs_lo + base + 8) = vl1;
        }
        __syncthreads();

        #pragma unroll
        for (int ks = 0; ks < 2; ks++) {
            Frag f;
            uint32_t ko = ks * 32;   // 16 bf16 cols = 32 bytes
            #pragma unroll
            for (int mt = 0; mt < 4; mt++) {
                LDSM_X4(f.ah[mt][0], f.ah[mt][1], f.ah[mt][2], f.ah[mt][3], sAhi + mt*16*RS*2 + ko);
                LDSM_X4(f.al[mt][0], f.al[mt][1], f.al[mt][2], f.al[mt][3], sAlo + mt*16*RS*2 + ko);
            }
            #pragma unroll
            for (int nt = 0; nt < 2; nt++) {
                LDSM_X4(f.bh[nt][0], f.bh[nt][1], f.bh[nt][2], f.bh[nt][3], sBhi + nt*16*RS*2 + ko);
                LDSM_X4(f.bl[nt][0], f.bl[nt][1], f.bl[nt][2], f.bl[nt][3], sBlo + nt*16*RS*2 + ko);
            }
            #pragma unroll
            for (int mt = 0; mt < 4; mt++)
                #pragma unroll
                for (int nt = 0; nt < 2; nt++)
                    #pragma unroll
                    for (int sub = 0; sub < 2; sub++) {
                        float* d = acc[mt][nt*2+sub];
                        MMA_BF16(d, f.ah[mt], f.bh[nt][sub], f.bh[nt][sub+2]);
                        MMA_BF16(d, f.ah[mt], f.bl[nt][sub], f.bl[nt][sub+2]);
                        MMA_BF16(d, f.al[mt], f.bh[nt][sub], f.bh[nt][sub+2]);
                    }
        }
        __syncthreads();
    }

    // ---- epilogue: bias + ReLU -> bf16 hi/lo h ----
    #pragma unroll
    for (int mt = 0; mt < 4; mt++) {
        int r0 = bm + warp_m*64 + mt*16 + (lane >> 2);
        #pragma unroll
        for (int f = 0; f < 4; f++) {
            int c = bn + warp_n*32 + f*8 + (lane & 3)*2;
            float2 bb = *(const float2*)(b1 + c);
            float v0 = fmaxf(acc[mt][f][0] + bb.x, 0.0f);
            float v1 = fmaxf(acc[mt][f][1] + bb.y, 0.0f);
            float v2 = fmaxf(acc[mt][f][2] + bb.x, 0.0f);
            float v3 = fmaxf(acc[mt][f][3] + bb.y, 0.0f);
            uint32_t hi, lo;
            split2(v0, v1, hi, lo);
            *(uint32_t*)(g_h_hi + (size_t)r0 * OUTD + c) = hi;
            *(uint32_t*)(g_h_lo + (size_t)r0 * OUTD + c) = lo;
            split2(v2, v3, hi, lo);
            *(uint32_t*)(g_h_hi + (size_t)(r0+8) * OUTD + c) = hi;
            *(uint32_t*)(g_h_lo + (size_t)(r0+8) * OUTD + c) = lo;
        }
    }
}

// ---------------- 3) mma.sync GEMM2: Linear2 + ReLU ----------------
__global__ __launch_bounds__(256)
void gemm2_kernel(const float* __restrict__ b2, float* __restrict__ out) {
    __shared__ __nv_bfloat16 As_hi[128*RS], As_lo[128*RS];
    __shared__ __nv_bfloat16 Bs_hi[128*RS], Bs_lo[128*RS];

    int tid = threadIdx.x;
    int wid = tid >> 5;
    int lane = tid & 31;
    int warp_m = wid & 1;
    int warp_n = wid >> 1;
    int bm = blockIdx.y * 128;
    int bn = blockIdx.x * 128;

    int lrow = tid >> 1;
    int lhalf = tid & 1;
    int r = bm + lrow;
    int nrow = bn + lrow;

    uint32_t aOff = (uint32_t)(((warp_m*64 + (lane & 15)) * RS + (lane >> 4) * 8) * 2);
    uint32_t bOff = (uint32_t)(((warp_n*32 + (lane & 15)) * RS + (lane >> 4) * 8) * 2);
    uint32_t sAhi = smem_u32(As_hi) + aOff, sAlo = smem_u32(As_lo) + aOff;
    uint32_t sBhi = smem_u32(Bs_hi) + bOff, sBlo = smem_u32(Bs_lo) + bOff;

    float acc[4][4][4];
    #pragma unroll
    for (int i = 0; i < 4; i++)
        #pragma unroll
        for (int j = 0; j < 4; j++)
            #pragma unroll
            for (int q = 0; q < 4; q++) acc[i][j][q] = 0.0f;

    for (int kt = 0; kt < OUTD; kt += 32) {
        {
            const __nv_bfloat16* sh = g_h_hi + (size_t)r * OUTD + kt + lhalf * 16;
            const __nv_bfloat16* sl = g_h_lo + (size_t)r * OUTD + kt + lhalf * 16;
            uint4 vh0 = *(const uint4*)(sh);
            uint4 vh1 = *(const uint4*)(sh + 8);
            uint4 vl0 = *(const uint4*)(sl);
            uint4 vl1 = *(const uint4*)(sl + 8);
            int base = lrow * RS + lhalf * 16;
            *(uint4*)(As_hi + base)     = vh0;
            *(uint4*)(As_hi + base + 8) = vh1;
            *(uint4*)(As_lo + base)     = vl0;
            *(uint4*)(As_lo + base + 8) = vl1;
        }
        {
            const __nv_bfloat16* sh = g_w2t_hi + (size_t)nrow * OUTD + kt + lhalf * 16;
            const __nv_bfloat16* sl = g_w2t_lo + (size_t)nrow * OUTD + kt + lhalf * 16;
            uint4 vh0 = *(const uint4*)(sh);
            uint4 vh1 = *(const uint4*)(sh + 8);
            uint4 vl0 = *(const uint4*)(sl);
            uint4 vl1 = *(const uint4*)(sl + 8);
            int base = lrow * RS + lhalf * 16;
            *(uint4*)(Bs_hi + base)     = vh0;
            *(uint4*)(Bs_hi + base + 8) = vh1;
            *(uint4*)(Bs_lo + base)     = vl0;
            *(uint4*)(Bs_lo + base + 8) = vl1;
        }
        __syncthreads();

        #pragma unroll
        for (int ks = 0; ks < 2; ks++) {
            Frag f;
            uint32_t ko = ks * 32;
            #pragma unroll
            for (int mt = 0; mt < 4; mt++) {
                LDSM_X4(f.ah[mt][0], f.ah[mt][1], f.ah[mt][2], f.ah[mt][3], sAhi + mt*16*RS*2 + ko);
                LDSM_X4(f.al[mt][0], f.al[mt][1], f.al[mt][2], f.al[mt][3], sAlo + mt*16*RS*2 + ko);
            }
            #pragma unroll
            for (int nt = 0; nt < 2; nt++) {
                LDSM_X4(f.bh[nt][0], f.bh[nt][1], f.bh[nt][2], f.bh[nt][3], sBhi + nt*16*RS*2 + ko);
                LDSM_X4(f.bl[nt][0], f.bl[nt][1], f.bl[nt][2], f.bl[nt][3], sBlo + nt*16*RS*2 + ko);
            }
            #pragma unroll
            for (int mt = 0; mt < 4; mt++)
                #pragma unroll
                for (int nt = 0; nt < 2; nt++)
                    #pragma unroll
                    for (int sub = 0; sub < 2; sub++) {
                        float* d = acc[mt][nt*2+sub];
                        MMA_BF16(d, f.ah[mt], f.bh[nt][sub], f.bh[nt][sub+2]);
                        MMA_BF16(d, f.ah[mt], f.bl[nt][sub], f.bl[nt][sub+2]);
                        MMA_BF16(d, f.al[mt], f.bh[nt][sub], f.bh[nt][sub+2]);
                    }
        }
        __syncthreads();
    }

    // ---- epilogue: bias + ReLU -> fp32 out ----
    #pragma unroll
    for (int mt = 0; mt < 4; mt++) {
        int r0 = bm + warp_m*64 + mt*16 + (lane >> 2);
        #pragma unroll
        for (int f = 0; f < 4; f++) {
            int c = bn + warp_n*32 + f*8 + (lane & 3)*2;
            float2 bb = *(const float2*)(b2 + c);
            float2 o0, o1;
            o0.x = fmaxf(acc[mt][f][0] + bb.x, 0.0f);
            o0.y = fmaxf(acc[mt][f][1] + bb.y, 0.0f);
            o1.x = fmaxf(acc[mt][f][2] + bb.x, 0.0f);
            o1.y = fmaxf(acc[mt][f][3] + bb.y, 0.0f);
            *(float2*)(out + (size_t)r0 * OUTD + c) = o0;
            *(float2*)(out + (size_t)(r0+8) * OUTD + c) = o1;
        }
    }
}

// ---------------- 4) tail: pos_skip (f32) + batch_skip (int32 in, f32 out) ----------------
__global__ void aux_kernel(const float* __restrict__ pos_skip,
                           const int* __restrict__ batch_skip,
                           float* __restrict__ out) {
    int i = blockIdx.x * blockDim.x + threadIdx.x;
    if (i < MTOT*3) out[HSIZE + i] = pos_skip[i];
    if (i < MTOT)   out[HSIZE + MTOT*3 + i] = (float)batch_skip[i];
}

// ---------------- launch ----------------
extern "C" void kernel_launch(void* const* d_in, const int* in_sizes, int n_in,
                              void* d_out, int out_size) {
    const float* x          = (const float*)d_in[0];
    const float* pos        = (const float*)d_in[1];
    const float* x_skip     = (const float*)d_in[3];
    const float* pos_skip   = (const float*)d_in[4];
    const int*   batch_skip = (const int*)d_in[5];
    const float* W1         = (const float*)d_in[6];
    const float* b1         = (const float*)d_in[7];
    const float* W2         = (const float*)d_in[8];
    const float* b2         = (const float*)d_in[9];
    float* out = (float*)d_out;

    knn_kernel<<<NB*32, 256>>>(pos, pos_skip);
    prep_kernel<<<(OUTD*K1 + 255)/256, 256>>>(W1, W2);
    gemm1_kernel<<<dim3(2, MTOT/128), 256>>>(x, x_skip, b1);
    gemm2_kernel<<<dim3(2, MTOT/128), 256>>>(b2, out);
    aux_kernel<<<(MTOT*3 + 255)/256, 256>>>(pos_skip, batch_skip, out);
}